// round 11
// baseline (speedup 1.0000x reference)
#include <cuda_runtime.h>
#include <cuda_bf16.h>
#include <math.h>
#include <stdint.h>

#define B_    8
#define S_    2048
#define H_    512
#define G4_   2048
#define NBLK  128

// ---------------------------------------------------------------------------
// Static device scratch (no allocation allowed)
// ---------------------------------------------------------------------------
__device__ float    g_xp[(size_t)B_ * S_ * G4_];      // 128 MiB
__device__ float    g_lstm[(size_t)B_ * S_ * H_];     // 32 MiB
__device__ float    g_scores[(size_t)B_ * S_ * H_];   // 32 MiB
__device__ float    g_logits[(size_t)B_ * S_ * S_];   // 128 MiB
__device__ float    g_hbuf[2][B_ * H_];               // h ping-pong
__device__ unsigned g_bar[S_];                        // per-step barrier counters

// bf16-split operand buffers
__device__ __align__(16) __nv_bfloat16 g_bufA[(size_t)16384 * 1536];   // 50 MiB
__device__ __align__(16) __nv_bfloat16 g_bufW[(size_t)2048 * 1536];    // 6 MiB
__device__ __align__(16) __nv_bfloat16 g_bufBIG[(size_t)16384 * 6144]; // 201 MiB
__device__ __align__(16) __nv_bfloat16 g_bufT[(size_t)8 * 512 * 6144]; // 50 MiB

// gathered split-bf16 W_hh for the recurrence: [128 blk][16 rows][512 k]
__device__ __align__(16) __nv_bfloat16 g_Whi[(size_t)128 * 16 * 512];  // 2 MiB
__device__ __align__(16) __nv_bfloat16 g_Wlo[(size_t)128 * 16 * 512];  // 2 MiB

__device__ __forceinline__ float sigm(float x) { return 1.0f / (1.0f + expf(-x)); }

__device__ __forceinline__ uint32_t smem_u32(const void* p) {
    uint32_t a;
    asm("{ .reg .u64 t; cvta.to.shared.u64 t, %1; cvt.u32.u64 %0, t; }"
        : "=r"(a) : "l"(p));
    return a;
}

__device__ __forceinline__ void ldm_x4(uint32_t* r, uint32_t addr) {
    asm volatile("ldmatrix.sync.aligned.m8n8.x4.shared.b16 {%0,%1,%2,%3}, [%4];"
        : "=r"(r[0]), "=r"(r[1]), "=r"(r[2]), "=r"(r[3]) : "r"(addr));
}
__device__ __forceinline__ void ldm_x2t(uint32_t* r, uint32_t addr) {
    asm volatile("ldmatrix.sync.aligned.m8n8.x2.trans.shared.b16 {%0,%1}, [%2];"
        : "=r"(r[0]), "=r"(r[1]) : "r"(addr));
}

__device__ __forceinline__ void mma16816(float* c, const uint32_t* a,
                                         const uint32_t* b) {
    asm volatile(
        "mma.sync.aligned.m16n8k16.row.col.f32.bf16.bf16.f32 "
        "{%0,%1,%2,%3}, {%4,%5,%6,%7}, {%8,%9}, {%0,%1,%2,%3};"
        : "+f"(c[0]), "+f"(c[1]), "+f"(c[2]), "+f"(c[3])
        : "r"(a[0]), "r"(a[1]), "r"(a[2]), "r"(a[3]), "r"(b[0]), "r"(b[1]));
}

// swizzled byte offset of row j in the hT buffer (16B rows, conflict-free)
#define HSW(j) ((uint32_t)((j) * 16) ^ ((((uint32_t)(j) >> 3) & 7u) << 4))

// ---------------------------------------------------------------------------
// Zero barrier counters + initial hidden state
// ---------------------------------------------------------------------------
__global__ void zero_kernel() {
    int i = blockIdx.x * 256 + threadIdx.x;
    if (i < S_) g_bar[i] = 0u;
    float* hb = &g_hbuf[0][0];
    if (i < 2 * B_ * H_) hb[i] = 0.0f;
}

// ---------------------------------------------------------------------------
// Gather + split W_hh into per-block row order: lr = gate*4 + jj
// ---------------------------------------------------------------------------
__global__ void __launch_bounds__(256)
cvt_whh(const float* __restrict__ W)
{
    size_t o = ((size_t)blockIdx.x * 256 + threadIdx.x) * 2;  // 2048 blocks
    int k  = (int)(o & 511);
    int lr = (int)((o >> 9) & 15);
    int blk = (int)(o >> 13);
    int gi = lr >> 2, jj = lr & 3;
    float2 x = *(const float2*)&W[(size_t)(gi * 512 + blk * 4 + jj) * 512 + k];
    __nv_bfloat16 h0 = __float2bfloat16(x.x);
    __nv_bfloat16 h1 = __float2bfloat16(x.y);
    __nv_bfloat16 l0 = __float2bfloat16(x.x - __bfloat162float(h0));
    __nv_bfloat16 l1 = __float2bfloat16(x.y - __bfloat162float(h1));
    __nv_bfloat162 Hv; Hv.x = h0; Hv.y = h1;
    __nv_bfloat162 Lv; Lv.x = l0; Lv.y = l1;
    *(__nv_bfloat162*)(g_Whi + o) = Hv;
    *(__nv_bfloat162*)(g_Wlo + o) = Lv;
}

// ---------------------------------------------------------------------------
// fp32 -> split-bf16 conversion, contiguous [R,K] -> [R,3K]
// amode=1 (A operand): segments (hi, lo, hi)
// amode=0 (B operand): segments (hi, hi, lo)
// ---------------------------------------------------------------------------
__global__ void __launch_bounds__(256)
cvt_split(const float* __restrict__ in, __nv_bfloat16* __restrict__ out,
          int K, int amode)
{
    size_t e = ((size_t)blockIdx.x * 256 + threadIdx.x) * 2;
    size_t r = e / (size_t)K;
    int k = (int)(e - r * (size_t)K);
    float2 x = *(const float2*)(in + e);
    __nv_bfloat16 h0 = __float2bfloat16(x.x);
    __nv_bfloat16 h1 = __float2bfloat16(x.y);
    __nv_bfloat16 l0 = __float2bfloat16(x.x - __bfloat162float(h0));
    __nv_bfloat16 l1 = __float2bfloat16(x.y - __bfloat162float(h1));
    __nv_bfloat162 Hv; Hv.x = h0; Hv.y = h1;
    __nv_bfloat162 Lv; Lv.x = l0; Lv.y = l1;
    __nv_bfloat16* o = out + r * (size_t)(3 * K) + k;
    *(__nv_bfloat162*)o = Hv;
    *(__nv_bfloat162*)(o + K) = amode ? Lv : Hv;
    *(__nv_bfloat162*)(o + 2 * K) = amode ? Hv : Lv;
}

// lstm [b][t][h] -> transposed split-bf16 B operand g_bufT[b][h][3*2048] (hi,hi,lo)
__global__ void __launch_bounds__(256)
cvt_lstmT()
{
    int idx = blockIdx.x * 256 + threadIdx.x;    // 8*512*1024
    int t2 = idx & 1023;
    int n  = (idx >> 10) & 511;
    int b  = idx >> 19;
    int t  = t2 * 2;
    const float* src = g_lstm + ((size_t)(b * 2048 + t)) * 512 + n;
    float x0 = src[0], x1 = src[512];
    __nv_bfloat16 h0 = __float2bfloat16(x0);
    __nv_bfloat16 h1 = __float2bfloat16(x1);
    __nv_bfloat16 l0 = __float2bfloat16(x0 - __bfloat162float(h0));
    __nv_bfloat16 l1 = __float2bfloat16(x1 - __bfloat162float(h1));
    __nv_bfloat162 Hv; Hv.x = h0; Hv.y = h1;
    __nv_bfloat162 Lv; Lv.x = l0; Lv.y = l1;
    __nv_bfloat16* o = g_bufT + ((size_t)(b * 512 + n)) * 6144 + t;
    *(__nv_bfloat162*)o = Hv;
    *(__nv_bfloat162*)(o + 2048) = Hv;
    *(__nv_bfloat162*)(o + 4096) = Lv;
}

// ---------------------------------------------------------------------------
// Tensor-core bf16 GEMM via mma.sync (unchanged from R10 — 331 TF/s measured)
// ---------------------------------------------------------------------------
__global__ void __launch_bounds__(128, 1)
mma_gemm(const __nv_bfloat16* __restrict__ A, const __nv_bfloat16* __restrict__ B,
         float* __restrict__ C,
         const float* __restrict__ bias, const float* __restrict__ bias2,
         int K3, int ldc, size_t sA, size_t sB, size_t sC)
{
    __shared__ __align__(16) char sm[2][2][128 * 80];

    const int z = blockIdx.z;
    A += (size_t)z * sA;
    B += (size_t)z * sB;
    C += (size_t)z * sC;
    const int m0 = blockIdx.y * 128;
    const int n0 = blockIdx.x * 128;

    const int tid = threadIdx.x;
    const int lane = tid & 31;
    const int wid = tid >> 5;
    const int wm = wid & 1;
    const int wn = wid >> 1;

    const int NC = K3 >> 5;

    float acc[4][8][4];
#pragma unroll
    for (int i = 0; i < 4; i++)
#pragma unroll
        for (int j = 0; j < 8; j++)
#pragma unroll
            for (int q = 0; q < 4; q++) acc[i][j][q] = 0.0f;

#define LOAD_STAGE(st, ck) do {                                               \
        _Pragma("unroll")                                                     \
        for (int _i = 0; _i < 8; _i++) {                                      \
            int _u = tid + _i * 128;                                          \
            int _ab = _u >> 9;                                                \
            int _v = _u & 511;                                                \
            int _r = _v >> 2, _cu = _v & 3;                                   \
            const __nv_bfloat16* _g = _ab                                     \
                ? B + (size_t)(n0 + _r) * K3 + (ck) * 32 + _cu * 8            \
                : A + (size_t)(m0 + _r) * K3 + (ck) * 32 + _cu * 8;           \
            uint32_t _s = smem_u32(&sm[st][_ab][_r * 80 + _cu * 16]);         \
            asm volatile("cp.async.cg.shared.global [%0], [%1], 16;"          \
                         :: "r"(_s), "l"(_g));                                \
        }                                                                     \
        asm volatile("cp.async.commit_group;" ::: "memory");                  \
    } while (0)

    LOAD_STAGE(0, 0);

    const int a_row_in = (lane & 15);
    const int a_koff   = (lane >> 4) * 16;
    const int b_row_in = (lane & 7) + ((lane >> 4) << 3);
    const int b_koff   = ((lane >> 3) & 1) * 16;

    for (int c = 0; c < NC; c++) {
        const int buf = c & 1;
        if (c + 1 < NC) {
            LOAD_STAGE(buf ^ 1, c + 1);
            asm volatile("cp.async.wait_group 1;" ::: "memory");
        } else {
            asm volatile("cp.async.wait_group 0;" ::: "memory");
        }
        __syncthreads();

        const uint32_t sAb = smem_u32(&sm[buf][0][0]);
        const uint32_t sBb = smem_u32(&sm[buf][1][0]);

#pragma unroll
        for (int s = 0; s < 2; s++) {
            uint32_t a[4][4];
#pragma unroll
            for (int mi = 0; mi < 4; mi++) {
                uint32_t addr = sAb +
                    (uint32_t)(wm * 64 + mi * 16 + a_row_in) * 80 +
                    s * 32 + a_koff;
                ldm_x4(a[mi], addr);
            }
            uint32_t b[8][2];
#pragma unroll
            for (int t4 = 0; t4 < 4; t4++) {
                uint32_t r[4];
                uint32_t addr = sBb +
                    (uint32_t)(wn * 64 + t4 * 16 + b_row_in) * 80 +
                    s * 32 + b_koff;
                ldm_x4(r, addr);
                b[2 * t4][0] = r[0]; b[2 * t4][1] = r[1];
                b[2 * t4 + 1][0] = r[2]; b[2 * t4 + 1][1] = r[3];
            }
#pragma unroll
            for (int mi = 0; mi < 4; mi++)
#pragma unroll
                for (int nj = 0; nj < 8; nj++)
                    mma16816(acc[mi][nj], a[mi], b[nj]);
        }
        __syncthreads();
    }

    const int g = lane >> 2, tig = lane & 3;
#pragma unroll
    for (int mi = 0; mi < 4; mi++) {
        const int r0 = m0 + wm * 64 + mi * 16 + g;
#pragma unroll
        for (int nj = 0; nj < 8; nj++) {
            const int col = n0 + wn * 64 + nj * 8 + tig * 2;
            float b0 = 0.0f, b1 = 0.0f;
            if (bias)  { b0 += bias[col];  b1 += bias[col + 1]; }
            if (bias2) { b0 += bias2[col]; b1 += bias2[col + 1]; }
            float2 v0 = make_float2(acc[mi][nj][0] + b0, acc[mi][nj][1] + b1);
            float2 v1 = make_float2(acc[mi][nj][2] + b0, acc[mi][nj][3] + b1);
            *(float2*)(C + (size_t)r0 * ldc + col) = v0;
            *(float2*)(C + (size_t)(r0 + 8) * ldc + col) = v1;
        }
    }
#undef LOAD_STAGE
}

// ---------------------------------------------------------------------------
// Persistent LSTM recurrence v3 — tensor cores.
// G[2048,8] = W_hh @ h^T per step. 128 blocks x 256 threads (8 warps).
// Block owns 16 gate-rows (lr = gate*4+jj for j = blk*4+jj). W fragments
// (split bf16 hi/lo) live in REGISTERS for the whole kernel. Per step:
// h staged as swizzled bf16 hi/lo in SMEM, warp w covers k in [w*64,w*64+64),
// 12 mma.sync per warp (Whi*hhi + Wlo*hhi + Whi*hlo), k-reduce in SMEM,
// activation by 32 threads, grid barrier.
// ---------------------------------------------------------------------------
__global__ void __launch_bounds__(256, 1)
lstm_rec_kernel()
{
    __shared__ __align__(16) char  s_hT[16384];   // hi @0 (8KB), lo @8192; also W stage
    __shared__ float s_red[8][16][8];             // per-warp 16x8 partials
    __shared__ float s_cs[32];                    // cell state (b*4+q)

    const int tid  = threadIdx.x;
    const int blk  = blockIdx.x;
    const int j0   = blk * 4;
    const int w    = tid >> 5;
    const int lane = tid & 31;

    const uint32_t hT_u32 = smem_u32(s_hT);

    // ---- startup: load W fragments into registers (once)
    uint32_t whi[4][4], wlo[4][4];
    {
        const uint4* srcH = (const uint4*)(g_Whi + (size_t)blk * 8192);
        uint4* dst = (uint4*)s_hT;
        for (int i = tid; i < 1024; i += 256) dst[i] = srcH[i];
        __syncthreads();
#pragma unroll
        for (int kw = 0; kw < 4; kw++) {
            uint32_t addr = hT_u32 + (uint32_t)(lane & 15) * 1024 +
                            (uint32_t)(w * 64 + kw * 16) * 2 + ((lane >> 4) * 16);
            ldm_x4(whi[kw], addr);
        }
        __syncthreads();
        const uint4* srcL = (const uint4*)(g_Wlo + (size_t)blk * 8192);
        for (int i = tid; i < 1024; i += 256) dst[i] = srcL[i];
        __syncthreads();
#pragma unroll
        for (int kw = 0; kw < 4; kw++) {
            uint32_t addr = hT_u32 + (uint32_t)(lane & 15) * 1024 +
                            (uint32_t)(w * 64 + kw * 16) * 2 + ((lane >> 4) * 16);
            ldm_x4(wlo[kw], addr);
        }
    }
    if (tid < 32) s_cs[tid] = 0.0f;
    __syncthreads();

    const int hb = tid & 7;            // batch for h staging
    const int J0 = (tid >> 3) * 16;    // j range for h staging

    for (int t = 0; t < S_; t++) {
        const int cur = t & 1;

        // xp prefetch (overlaps everything until activation)
        float xi = 0.f, xf = 0.f, xg = 0.f, xo = 0.f;
        if (tid < 32) {
            int b = tid >> 2, q = tid & 3;
            size_t base = ((size_t)b * S_ + t) * G4_ + (j0 + q);
            xi = g_xp[base];
            xf = g_xp[base + 512];
            xg = g_xp[base + 1024];
            xo = g_xp[base + 1536];
        }

        // stage h: fp32 (L2) -> swizzled bf16 hi/lo transposed [j][b]
        {
            const float* hp = &g_hbuf[cur][hb * 512 + J0];
            float4 v0 = __ldcg((const float4*)hp);
            float4 v1 = __ldcg((const float4*)(hp + 4));
            float4 v2 = __ldcg((const float4*)(hp + 8));
            float4 v3 = __ldcg((const float4*)(hp + 12));
            float xs[16] = {v0.x, v0.y, v0.z, v0.w, v1.x, v1.y, v1.z, v1.w,
                            v2.x, v2.y, v2.z, v2.w, v3.x, v3.y, v3.z, v3.w};
#pragma unroll
            for (int i = 0; i < 16; i++) {
                int j = J0 + i;
                uint32_t off = HSW(j) + hb * 2;
                __nv_bfloat16 hi = __float2bfloat16(xs[i]);
                __nv_bfloat16 lo = __float2bfloat16(xs[i] - __bfloat162float(hi));
                *(__nv_bfloat16*)(s_hT + off) = hi;
                *(__nv_bfloat16*)(s_hT + 8192 + off) = lo;
            }
        }
        __syncthreads();

        // 12 mma.sync: acc = Whi*hhi, acc2 = Wlo*hhi + Whi*hlo
        float acc[4] = {0.f, 0.f, 0.f, 0.f};
        float acc2[4] = {0.f, 0.f, 0.f, 0.f};
#pragma unroll
        for (int kw = 0; kw < 4; kw++) {
            const int k0 = w * 64 + kw * 16;
            uint32_t bh[2], bl[2];
            uint32_t ab = hT_u32 + HSW(k0 + (lane & 15));
            ldm_x2t(bh, ab);
            ldm_x2t(bl, ab + 8192);
            mma16816(acc,  whi[kw], bh);
            mma16816(acc2, wlo[kw], bh);
            mma16816(acc2, whi[kw], bl);
        }
        {
            const int row = lane >> 2, col = (lane & 3) * 2;
            *(float2*)&s_red[w][row][col] =
                make_float2(acc[0] + acc2[0], acc[1] + acc2[1]);
            *(float2*)&s_red[w][row + 8][col] =
                make_float2(acc[2] + acc2[2], acc[3] + acc2[3]);
        }
        __syncthreads();

        // activation: thread (b,q)
        if (tid < 32) {
            int b = tid >> 2, q = tid & 3;
            float gsum[4];
#pragma unroll
            for (int g = 0; g < 4; g++) {
                float s = 0.0f;
#pragma unroll
                for (int w2 = 0; w2 < 8; w2++) s += s_red[w2][g * 4 + q][b];
                gsum[g] = s;
            }
            float ig = gsum[0] + xi;
            float fg = gsum[1] + xf;
            float gg = gsum[2] + xg;
            float og = gsum[3] + xo;
            float cc = sigm(fg) * s_cs[tid] + sigm(ig) * tanhf(gg);
            float hh = sigm(og) * tanhf(cc);
            s_cs[tid] = cc;
            int j = j0 + q;
            g_hbuf[cur ^ 1][b * H_ + j] = hh;
            g_lstm[((size_t)b * S_ + t) * H_ + j] = hh;
        }

        // grid barrier
        __threadfence();
        __syncthreads();
        if (tid == 0) {
            atomicAdd(&g_bar[t], 1u);
            volatile unsigned* p = &g_bar[t];
            while (*p < (unsigned)NBLK) { __nanosleep(32); }
        }
        __syncthreads();
    }
}

// ---------------------------------------------------------------------------
// Row softmax over g_logits: 16384 rows of 2048.
// ---------------------------------------------------------------------------
__global__ void __launch_bounds__(256) softmax_kernel() {
    __shared__ float red[8];
    float* p = g_logits + (size_t)blockIdx.x * 2048;
    const int tid = threadIdx.x;

    float4 v0 = *(const float4*)(p + tid * 4);
    float4 v1 = *(const float4*)(p + 1024 + tid * 4);

    float m = fmaxf(fmaxf(fmaxf(v0.x, v0.y), fmaxf(v0.z, v0.w)),
                    fmaxf(fmaxf(v1.x, v1.y), fmaxf(v1.z, v1.w)));
#pragma unroll
    for (int off = 16; off; off >>= 1)
        m = fmaxf(m, __shfl_xor_sync(0xffffffffu, m, off));
    if ((tid & 31) == 0) red[tid >> 5] = m;
    __syncthreads();
    m = red[0];
#pragma unroll
    for (int w = 1; w < 8; w++) m = fmaxf(m, red[w]);
    __syncthreads();

    v0.x = expf(v0.x - m); v0.y = expf(v0.y - m);
    v0.z = expf(v0.z - m); v0.w = expf(v0.w - m);
    v1.x = expf(v1.x - m); v1.y = expf(v1.y - m);
    v1.z = expf(v1.z - m); v1.w = expf(v1.w - m);

    float s = v0.x + v0.y + v0.z + v0.w + v1.x + v1.y + v1.z + v1.w;
#pragma unroll
    for (int off = 16; off; off >>= 1)
        s += __shfl_xor_sync(0xffffffffu, s, off);
    if ((tid & 31) == 0) red[tid >> 5] = s;
    __syncthreads();
    s = red[0];
#pragma unroll
    for (int w = 1; w < 8; w++) s += red[w];

    float inv = 1.0f / s;
    v0.x *= inv; v0.y *= inv; v0.z *= inv; v0.w *= inv;
    v1.x *= inv; v1.y *= inv; v1.z *= inv; v1.w *= inv;
    *(float4*)(p + tid * 4) = v0;
    *(float4*)(p + 1024 + tid * 4) = v1;
}

// ---------------------------------------------------------------------------
// Launch
// ---------------------------------------------------------------------------
extern "C" void kernel_launch(void* const* d_in, const int* in_sizes, int n_in,
                              void* d_out, int out_size)
{
    const float* x    = (const float*)d_in[0];  // [B,S,I]
    const float* W_ih = (const float*)d_in[1];  // [4H,I]
    const float* W_hh = (const float*)d_in[2];  // [4H,H]
    const float* b_ih = (const float*)d_in[3];  // [4H]
    const float* b_hh = (const float*)d_in[4];  // [4H]
    const float* Wa   = (const float*)d_in[5];  // [H,H]
    const float* ba   = (const float*)d_in[6];  // [H]
    float* out = (float*)d_out;                 // [B,S,H] fp32

    void *p0, *p1, *p2, *p3, *pa, *pw, *pbig, *pt;
    cudaGetSymbolAddress(&p0, g_xp);
    cudaGetSymbolAddress(&p1, g_lstm);
    cudaGetSymbolAddress(&p2, g_scores);
    cudaGetSymbolAddress(&p3, g_logits);
    cudaGetSymbolAddress(&pa, g_bufA);
    cudaGetSymbolAddress(&pw, g_bufW);
    cudaGetSymbolAddress(&pbig, g_bufBIG);
    cudaGetSymbolAddress(&pt, g_bufT);
    float* xp_p     = (float*)p0;
    float* lstm_p   = (float*)p1;
    float* scores_p = (float*)p2;
    float* logits_p = (float*)p3;
    __nv_bfloat16* bufA   = (__nv_bfloat16*)pa;
    __nv_bfloat16* bufW   = (__nv_bfloat16*)pw;
    __nv_bfloat16* bufBIG = (__nv_bfloat16*)pbig;
    __nv_bfloat16* bufT   = (__nv_bfloat16*)pt;

    zero_kernel<<<32, 256>>>();
    cvt_whh<<<2048, 256>>>(W_hh);

    // 1) xp = x @ W_ih^T + b_ih + b_hh       M=16384, N=2048, K3=1536
    cvt_split<<<16384, 256>>>(x, bufA, 512, 1);
    cvt_split<<<2048, 256>>>(W_ih, bufW, 512, 0);
    mma_gemm<<<dim3(16, 128, 1), 128>>>(
        bufA, bufW, xp_p, b_ih, b_hh, 1536, 2048, 0, 0, 0);

    // 2) persistent LSTM recurrence (tensor-core)
    lstm_rec_kernel<<<NBLK, 256>>>();

    // 3) scores = lstm @ Wa^T + ba           M=16384, N=512, K3=1536
    cvt_split<<<16384, 256>>>(lstm_p, bufA, 512, 1);
    cvt_split<<<512, 256>>>(Wa, bufW, 512, 0);
    mma_gemm<<<dim3(4, 128, 1), 128>>>(
        bufA, bufW, scores_p, ba, nullptr, 1536, 512, 0, 0, 0);

    // 4) logits[b] = scores[b] @ scores[b]^T M=2048, N=2048, K3=1536, batched
    cvt_split<<<16384, 256>>>(scores_p, bufA, 512, 1);
    cvt_split<<<16384, 256>>>(scores_p, bufBIG, 512, 0);
    mma_gemm<<<dim3(16, 16, 8), 128>>>(
        bufA, bufBIG, logits_p, nullptr, nullptr, 1536, 2048,
        (size_t)2048 * 1536, (size_t)2048 * 1536, (size_t)2048 * 2048);

    // 5) att = softmax(logits) in place
    softmax_kernel<<<16384, 256>>>();

    // 6) out[b] = att[b] @ lstm[b]           M=2048, N=512, K3=6144, batched
    cvt_split<<<65536, 256>>>(logits_p, bufBIG, 2048, 1);
    cvt_lstmT<<<16384, 256>>>();
    mma_gemm<<<dim3(4, 16, 8), 128>>>(
        bufBIG, bufT, out, nullptr, nullptr, 6144, 512,
        (size_t)2048 * 6144, (size_t)512 * 6144, (size_t)2048 * 512);
}

// round 12
// speedup vs baseline: 1.2466x; 1.2466x over previous
#include <cuda_runtime.h>
#include <cuda_bf16.h>
#include <math.h>
#include <stdint.h>

#define B_    8
#define S_    2048
#define H_    512
#define G4_   2048
#define NBLK  128

// ---------------------------------------------------------------------------
// Static device scratch (no allocation allowed)
// ---------------------------------------------------------------------------
__device__ float    g_xp[(size_t)B_ * S_ * G4_];      // 128 MiB
__device__ float    g_lstm[(size_t)B_ * S_ * H_];     // 32 MiB
__device__ float    g_scores[(size_t)B_ * S_ * H_];   // 32 MiB
__device__ float    g_logits[(size_t)B_ * S_ * S_];   // 128 MiB
__device__ float    g_hbuf[2][B_ * H_];               // h ping-pong
__device__ unsigned g_bar[S_];                        // per-step barrier counters

// bf16-split operand buffers
__device__ __align__(16) __nv_bfloat16 g_bufA[(size_t)16384 * 1536];   // 50 MiB
__device__ __align__(16) __nv_bfloat16 g_bufW[(size_t)2048 * 1536];    // 6 MiB
__device__ __align__(16) __nv_bfloat16 g_bufBIG[(size_t)16384 * 6144]; // 201 MiB
__device__ __align__(16) __nv_bfloat16 g_bufT[(size_t)8 * 512 * 6144]; // 50 MiB

// gathered split-bf16 W_hh for the recurrence: [128 blk][16 rows][512 k]
__device__ __align__(16) __nv_bfloat16 g_Whi[(size_t)128 * 16 * 512];  // 2 MiB
__device__ __align__(16) __nv_bfloat16 g_Wlo[(size_t)128 * 16 * 512];  // 2 MiB

__device__ __forceinline__ float sigm(float x) { return 1.0f / (1.0f + expf(-x)); }

__device__ __forceinline__ uint32_t smem_u32(const void* p) {
    uint32_t a;
    asm("{ .reg .u64 t; cvta.to.shared.u64 t, %1; cvt.u32.u64 %0, t; }"
        : "=r"(a) : "l"(p));
    return a;
}

__device__ __forceinline__ void ldm_x4(uint32_t* r, uint32_t addr) {
    asm volatile("ldmatrix.sync.aligned.m8n8.x4.shared.b16 {%0,%1,%2,%3}, [%4];"
        : "=r"(r[0]), "=r"(r[1]), "=r"(r[2]), "=r"(r[3]) : "r"(addr));
}
__device__ __forceinline__ void ldm_x2t(uint32_t* r, uint32_t addr) {
    asm volatile("ldmatrix.sync.aligned.m8n8.x2.trans.shared.b16 {%0,%1}, [%2];"
        : "=r"(r[0]), "=r"(r[1]) : "r"(addr));
}

__device__ __forceinline__ void mma16816(float* c, const uint32_t* a,
                                         const uint32_t* b) {
    asm volatile(
        "mma.sync.aligned.m16n8k16.row.col.f32.bf16.bf16.f32 "
        "{%0,%1,%2,%3}, {%4,%5,%6,%7}, {%8,%9}, {%0,%1,%2,%3};"
        : "+f"(c[0]), "+f"(c[1]), "+f"(c[2]), "+f"(c[3])
        : "r"(a[0]), "r"(a[1]), "r"(a[2]), "r"(a[3]), "r"(b[0]), "r"(b[1]));
}

// ---------------------------------------------------------------------------
// Zero barrier counters + initial hidden state
// ---------------------------------------------------------------------------
__global__ void zero_kernel() {
    int i = blockIdx.x * 256 + threadIdx.x;
    if (i < S_) g_bar[i] = 0u;
    float* hb = &g_hbuf[0][0];
    if (i < 2 * B_ * H_) hb[i] = 0.0f;
}

// ---------------------------------------------------------------------------
// Gather + split W_hh into per-block row order: lr = gate*4 + jj
// ---------------------------------------------------------------------------
__global__ void __launch_bounds__(256)
cvt_whh(const float* __restrict__ W)
{
    size_t o = ((size_t)blockIdx.x * 256 + threadIdx.x) * 2;  // 2048 blocks
    int k  = (int)(o & 511);
    int lr = (int)((o >> 9) & 15);
    int blk = (int)(o >> 13);
    int gi = lr >> 2, jj = lr & 3;
    float2 x = *(const float2*)&W[(size_t)(gi * 512 + blk * 4 + jj) * 512 + k];
    __nv_bfloat16 h0 = __float2bfloat16(x.x);
    __nv_bfloat16 h1 = __float2bfloat16(x.y);
    __nv_bfloat16 l0 = __float2bfloat16(x.x - __bfloat162float(h0));
    __nv_bfloat16 l1 = __float2bfloat16(x.y - __bfloat162float(h1));
    __nv_bfloat162 Hv; Hv.x = h0; Hv.y = h1;
    __nv_bfloat162 Lv; Lv.x = l0; Lv.y = l1;
    *(__nv_bfloat162*)(g_Whi + o) = Hv;
    *(__nv_bfloat162*)(g_Wlo + o) = Lv;
}

// ---------------------------------------------------------------------------
// fp32 -> split-bf16 conversion, contiguous [R,K] -> [R,3K]
// amode=1 (A operand): segments (hi, lo, hi)
// amode=0 (B operand): segments (hi, hi, lo)
// ---------------------------------------------------------------------------
__global__ void __launch_bounds__(256)
cvt_split(const float* __restrict__ in, __nv_bfloat16* __restrict__ out,
          int K, int amode)
{
    size_t e = ((size_t)blockIdx.x * 256 + threadIdx.x) * 2;
    size_t r = e / (size_t)K;
    int k = (int)(e - r * (size_t)K);
    float2 x = *(const float2*)(in + e);
    __nv_bfloat16 h0 = __float2bfloat16(x.x);
    __nv_bfloat16 h1 = __float2bfloat16(x.y);
    __nv_bfloat16 l0 = __float2bfloat16(x.x - __bfloat162float(h0));
    __nv_bfloat16 l1 = __float2bfloat16(x.y - __bfloat162float(h1));
    __nv_bfloat162 Hv; Hv.x = h0; Hv.y = h1;
    __nv_bfloat162 Lv; Lv.x = l0; Lv.y = l1;
    __nv_bfloat16* o = out + r * (size_t)(3 * K) + k;
    *(__nv_bfloat162*)o = Hv;
    *(__nv_bfloat162*)(o + K) = amode ? Lv : Hv;
    *(__nv_bfloat162*)(o + 2 * K) = amode ? Hv : Lv;
}

// lstm [b][t][h] -> transposed split-bf16 B operand g_bufT[b][h][3*2048] (hi,hi,lo)
__global__ void __launch_bounds__(256)
cvt_lstmT()
{
    int idx = blockIdx.x * 256 + threadIdx.x;    // 8*512*1024
    int t2 = idx & 1023;
    int n  = (idx >> 10) & 511;
    int b  = idx >> 19;
    int t  = t2 * 2;
    const float* src = g_lstm + ((size_t)(b * 2048 + t)) * 512 + n;
    float x0 = src[0], x1 = src[512];
    __nv_bfloat16 h0 = __float2bfloat16(x0);
    __nv_bfloat16 h1 = __float2bfloat16(x1);
    __nv_bfloat16 l0 = __float2bfloat16(x0 - __bfloat162float(h0));
    __nv_bfloat16 l1 = __float2bfloat16(x1 - __bfloat162float(h1));
    __nv_bfloat162 Hv; Hv.x = h0; Hv.y = h1;
    __nv_bfloat162 Lv; Lv.x = l0; Lv.y = l1;
    __nv_bfloat16* o = g_bufT + ((size_t)(b * 512 + n)) * 6144 + t;
    *(__nv_bfloat162*)o = Hv;
    *(__nv_bfloat162*)(o + 2048) = Hv;
    *(__nv_bfloat162*)(o + 4096) = Lv;
}

// ---------------------------------------------------------------------------
// Tensor-core bf16 GEMM via mma.sync (unchanged from R10 — 331 TF/s measured)
// ---------------------------------------------------------------------------
__global__ void __launch_bounds__(128, 1)
mma_gemm(const __nv_bfloat16* __restrict__ A, const __nv_bfloat16* __restrict__ B,
         float* __restrict__ C,
         const float* __restrict__ bias, const float* __restrict__ bias2,
         int K3, int ldc, size_t sA, size_t sB, size_t sC)
{
    __shared__ __align__(16) char sm[2][2][128 * 80];

    const int z = blockIdx.z;
    A += (size_t)z * sA;
    B += (size_t)z * sB;
    C += (size_t)z * sC;
    const int m0 = blockIdx.y * 128;
    const int n0 = blockIdx.x * 128;

    const int tid = threadIdx.x;
    const int lane = tid & 31;
    const int wid = tid >> 5;
    const int wm = wid & 1;
    const int wn = wid >> 1;

    const int NC = K3 >> 5;

    float acc[4][8][4];
#pragma unroll
    for (int i = 0; i < 4; i++)
#pragma unroll
        for (int j = 0; j < 8; j++)
#pragma unroll
            for (int q = 0; q < 4; q++) acc[i][j][q] = 0.0f;

#define LOAD_STAGE(st, ck) do {                                               \
        _Pragma("unroll")                                                     \
        for (int _i = 0; _i < 8; _i++) {                                      \
            int _u = tid + _i * 128;                                          \
            int _ab = _u >> 9;                                                \
            int _v = _u & 511;                                                \
            int _r = _v >> 2, _cu = _v & 3;                                   \
            const __nv_bfloat16* _g = _ab                                     \
                ? B + (size_t)(n0 + _r) * K3 + (ck) * 32 + _cu * 8            \
                : A + (size_t)(m0 + _r) * K3 + (ck) * 32 + _cu * 8;           \
            uint32_t _s = smem_u32(&sm[st][_ab][_r * 80 + _cu * 16]);         \
            asm volatile("cp.async.cg.shared.global [%0], [%1], 16;"          \
                         :: "r"(_s), "l"(_g));                                \
        }                                                                     \
        asm volatile("cp.async.commit_group;" ::: "memory");                  \
    } while (0)

    LOAD_STAGE(0, 0);

    const int a_row_in = (lane & 15);
    const int a_koff   = (lane >> 4) * 16;
    const int b_row_in = (lane & 7) + ((lane >> 4) << 3);
    const int b_koff   = ((lane >> 3) & 1) * 16;

    for (int c = 0; c < NC; c++) {
        const int buf = c & 1;
        if (c + 1 < NC) {
            LOAD_STAGE(buf ^ 1, c + 1);
            asm volatile("cp.async.wait_group 1;" ::: "memory");
        } else {
            asm volatile("cp.async.wait_group 0;" ::: "memory");
        }
        __syncthreads();

        const uint32_t sAb = smem_u32(&sm[buf][0][0]);
        const uint32_t sBb = smem_u32(&sm[buf][1][0]);

#pragma unroll
        for (int s = 0; s < 2; s++) {
            uint32_t a[4][4];
#pragma unroll
            for (int mi = 0; mi < 4; mi++) {
                uint32_t addr = sAb +
                    (uint32_t)(wm * 64 + mi * 16 + a_row_in) * 80 +
                    s * 32 + a_koff;
                ldm_x4(a[mi], addr);
            }
            uint32_t b[8][2];
#pragma unroll
            for (int t4 = 0; t4 < 4; t4++) {
                uint32_t r[4];
                uint32_t addr = sBb +
                    (uint32_t)(wn * 64 + t4 * 16 + b_row_in) * 80 +
                    s * 32 + b_koff;
                ldm_x4(r, addr);
                b[2 * t4][0] = r[0]; b[2 * t4][1] = r[1];
                b[2 * t4 + 1][0] = r[2]; b[2 * t4 + 1][1] = r[3];
            }
#pragma unroll
            for (int mi = 0; mi < 4; mi++)
#pragma unroll
                for (int nj = 0; nj < 8; nj++)
                    mma16816(acc[mi][nj], a[mi], b[nj]);
        }
        __syncthreads();
    }

    const int g = lane >> 2, tig = lane & 3;
#pragma unroll
    for (int mi = 0; mi < 4; mi++) {
        const int r0 = m0 + wm * 64 + mi * 16 + g;
#pragma unroll
        for (int nj = 0; nj < 8; nj++) {
            const int col = n0 + wn * 64 + nj * 8 + tig * 2;
            float b0 = 0.0f, b1 = 0.0f;
            if (bias)  { b0 += bias[col];  b1 += bias[col + 1]; }
            if (bias2) { b0 += bias2[col]; b1 += bias2[col + 1]; }
            float2 v0 = make_float2(acc[mi][nj][0] + b0, acc[mi][nj][1] + b1);
            float2 v1 = make_float2(acc[mi][nj][2] + b0, acc[mi][nj][3] + b1);
            *(float2*)(C + (size_t)r0 * ldc + col) = v0;
            *(float2*)(C + (size_t)(r0 + 8) * ldc + col) = v1;
        }
    }
#undef LOAD_STAGE
}

// ---------------------------------------------------------------------------
// Persistent LSTM recurrence v4 — tensor cores, rebuilt h staging.
// 128 blocks x 256 threads. Block owns 16 gate-rows; W fragments (split bf16)
// in registers for the whole kernel. h staged as LINEAR bf16 [j][8b] 16B rows
// (hi @0, lo @8192): one thread = one j-row, 4x STS.128, conflict-free;
// ldmatrix.trans reads 8 consecutive 16B rows = 128B per phase, conflict-free.
// Per step per warp: 8 ldm_x2t + 12 mma.sync, k-reduce in SMEM, activation,
// grid barrier.
// ---------------------------------------------------------------------------
__global__ void __launch_bounds__(256, 1)
lstm_rec_kernel()
{
    __shared__ __align__(16) char  s_hT[16384];   // hi @0 (8KB), lo @8192; W stage at startup
    __shared__ float s_red[8][16][8];             // per-warp 16x8 partials
    __shared__ float s_cs[32];                    // cell state (b*4+q)

    const int tid  = threadIdx.x;
    const int blk  = blockIdx.x;
    const int j0   = blk * 4;
    const int w    = tid >> 5;
    const int lane = tid & 31;

    const uint32_t hT_u32 = smem_u32(s_hT);

    // ---- startup: load W fragments into registers (once)
    uint32_t whi[4][4], wlo[4][4];
    {
        const uint4* srcH = (const uint4*)(g_Whi + (size_t)blk * 8192);
        uint4* dst = (uint4*)s_hT;
        for (int i = tid; i < 1024; i += 256) dst[i] = srcH[i];
        __syncthreads();
#pragma unroll
        for (int kw = 0; kw < 4; kw++) {
            uint32_t addr = hT_u32 + (uint32_t)(lane & 15) * 1024 +
                            (uint32_t)(w * 64 + kw * 16) * 2 + ((lane >> 4) * 16);
            ldm_x4(whi[kw], addr);
        }
        __syncthreads();
        const uint4* srcL = (const uint4*)(g_Wlo + (size_t)blk * 8192);
        for (int i = tid; i < 1024; i += 256) dst[i] = srcL[i];
        __syncthreads();
#pragma unroll
        for (int kw = 0; kw < 4; kw++) {
            uint32_t addr = hT_u32 + (uint32_t)(lane & 15) * 1024 +
                            (uint32_t)(w * 64 + kw * 16) * 2 + ((lane >> 4) * 16);
            ldm_x4(wlo[kw], addr);
        }
    }
    if (tid < 32) s_cs[tid] = 0.0f;
    __syncthreads();

    for (int t = 0; t < S_; t++) {
        const int cur = t & 1;

        // xp prefetch (overlaps everything until activation)
        float xi = 0.f, xf = 0.f, xg = 0.f, xo = 0.f;
        if (tid < 32) {
            int b = tid >> 2, q = tid & 3;
            size_t base = ((size_t)b * S_ + t) * G4_ + (j0 + q);
            xi = g_xp[base];
            xf = g_xp[base + 512];
            xg = g_xp[base + 1024];
            xo = g_xp[base + 1536];
        }

        // stage h: one thread = one j-row (2 rows/thread), linear layout,
        // coalesced LDG.32, pair bf16 converts, 4x STS.128 total.
#pragma unroll
        for (int rep = 0; rep < 2; rep++) {
            const int j = tid + rep * 256;
            const float* hp = &g_hbuf[cur][j];
            float v[8];
#pragma unroll
            for (int b = 0; b < 8; b++) v[b] = __ldcg(hp + b * 512);

            __nv_bfloat162 Hp[4];
            uint32_t LO[4];
#pragma unroll
            for (int p = 0; p < 4; p++) {
                Hp[p] = __float22bfloat162_rn(make_float2(v[2 * p], v[2 * p + 1]));
                float2 lp = make_float2(v[2 * p] - __low2float(Hp[p]),
                                        v[2 * p + 1] - __high2float(Hp[p]));
                __nv_bfloat162 L = __float22bfloat162_rn(lp);
                LO[p] = *(uint32_t*)&L;
            }
            uint4 HI4 = make_uint4(*(uint32_t*)&Hp[0], *(uint32_t*)&Hp[1],
                                   *(uint32_t*)&Hp[2], *(uint32_t*)&Hp[3]);
            uint4 LO4 = make_uint4(LO[0], LO[1], LO[2], LO[3]);
            *(uint4*)(s_hT + j * 16) = HI4;
            *(uint4*)(s_hT + 8192 + j * 16) = LO4;
        }
        __syncthreads();

        // 12 mma.sync: acc = Whi*hhi, acc2 = Wlo*hhi + Whi*hlo
        float acc[4] = {0.f, 0.f, 0.f, 0.f};
        float acc2[4] = {0.f, 0.f, 0.f, 0.f};
#pragma unroll
        for (int kw = 0; kw < 4; kw++) {
            const int k0 = w * 64 + kw * 16;
            uint32_t bh[2], bl[2];
            uint32_t ab = hT_u32 + (uint32_t)(k0 + (lane & 15)) * 16;
            ldm_x2t(bh, ab);
            ldm_x2t(bl, ab + 8192);
            mma16816(acc,  whi[kw], bh);
            mma16816(acc2, wlo[kw], bh);
            mma16816(acc2, whi[kw], bl);
        }
        {
            const int row = lane >> 2, col = (lane & 3) * 2;
            *(float2*)&s_red[w][row][col] =
                make_float2(acc[0] + acc2[0], acc[1] + acc2[1]);
            *(float2*)&s_red[w][row + 8][col] =
                make_float2(acc[2] + acc2[2], acc[3] + acc2[3]);
        }
        __syncthreads();

        // activation: thread (b,q)
        if (tid < 32) {
            int b = tid >> 2, q = tid & 3;
            float gsum[4];
#pragma unroll
            for (int g = 0; g < 4; g++) {
                float s = 0.0f;
#pragma unroll
                for (int w2 = 0; w2 < 8; w2++) s += s_red[w2][g * 4 + q][b];
                gsum[g] = s;
            }
            float ig = gsum[0] + xi;
            float fg = gsum[1] + xf;
            float gg = gsum[2] + xg;
            float og = gsum[3] + xo;
            float cc = sigm(fg) * s_cs[tid] + sigm(ig) * tanhf(gg);
            float hh = sigm(og) * tanhf(cc);
            s_cs[tid] = cc;
            int j = j0 + q;
            g_hbuf[cur ^ 1][b * H_ + j] = hh;
            g_lstm[((size_t)b * S_ + t) * H_ + j] = hh;
        }

        // grid barrier
        __threadfence();
        __syncthreads();
        if (tid == 0) {
            atomicAdd(&g_bar[t], 1u);
            volatile unsigned* p = &g_bar[t];
            while (*p < (unsigned)NBLK) { __nanosleep(32); }
        }
        __syncthreads();
    }
}

// ---------------------------------------------------------------------------
// Row softmax over g_logits: 16384 rows of 2048.
// ---------------------------------------------------------------------------
__global__ void __launch_bounds__(256) softmax_kernel() {
    __shared__ float red[8];
    float* p = g_logits + (size_t)blockIdx.x * 2048;
    const int tid = threadIdx.x;

    float4 v0 = *(const float4*)(p + tid * 4);
    float4 v1 = *(const float4*)(p + 1024 + tid * 4);

    float m = fmaxf(fmaxf(fmaxf(v0.x, v0.y), fmaxf(v0.z, v0.w)),
                    fmaxf(fmaxf(v1.x, v1.y), fmaxf(v1.z, v1.w)));
#pragma unroll
    for (int off = 16; off; off >>= 1)
        m = fmaxf(m, __shfl_xor_sync(0xffffffffu, m, off));
    if ((tid & 31) == 0) red[tid >> 5] = m;
    __syncthreads();
    m = red[0];
#pragma unroll
    for (int w = 1; w < 8; w++) m = fmaxf(m, red[w]);
    __syncthreads();

    v0.x = expf(v0.x - m); v0.y = expf(v0.y - m);
    v0.z = expf(v0.z - m); v0.w = expf(v0.w - m);
    v1.x = expf(v1.x - m); v1.y = expf(v1.y - m);
    v1.z = expf(v1.z - m); v1.w = expf(v1.w - m);

    float s = v0.x + v0.y + v0.z + v0.w + v1.x + v1.y + v1.z + v1.w;
#pragma unroll
    for (int off = 16; off; off >>= 1)
        s += __shfl_xor_sync(0xffffffffu, s, off);
    if ((tid & 31) == 0) red[tid >> 5] = s;
    __syncthreads();
    s = red[0];
#pragma unroll
    for (int w = 1; w < 8; w++) s += red[w];

    float inv = 1.0f / s;
    v0.x *= inv; v0.y *= inv; v0.z *= inv; v0.w *= inv;
    v1.x *= inv; v1.y *= inv; v1.z *= inv; v1.w *= inv;
    *(float4*)(p + tid * 4) = v0;
    *(float4*)(p + 1024 + tid * 4) = v1;
}

// ---------------------------------------------------------------------------
// Launch
// ---------------------------------------------------------------------------
extern "C" void kernel_launch(void* const* d_in, const int* in_sizes, int n_in,
                              void* d_out, int out_size)
{
    const float* x    = (const float*)d_in[0];  // [B,S,I]
    const float* W_ih = (const float*)d_in[1];  // [4H,I]
    const float* W_hh = (const float*)d_in[2];  // [4H,H]
    const float* b_ih = (const float*)d_in[3];  // [4H]
    const float* b_hh = (const float*)d_in[4];  // [4H]
    const float* Wa   = (const float*)d_in[5];  // [H,H]
    const float* ba   = (const float*)d_in[6];  // [H]
    float* out = (float*)d_out;                 // [B,S,H] fp32

    void *p0, *p1, *p2, *p3, *pa, *pw, *pbig, *pt;
    cudaGetSymbolAddress(&p0, g_xp);
    cudaGetSymbolAddress(&p1, g_lstm);
    cudaGetSymbolAddress(&p2, g_scores);
    cudaGetSymbolAddress(&p3, g_logits);
    cudaGetSymbolAddress(&pa, g_bufA);
    cudaGetSymbolAddress(&pw, g_bufW);
    cudaGetSymbolAddress(&pbig, g_bufBIG);
    cudaGetSymbolAddress(&pt, g_bufT);
    float* xp_p     = (float*)p0;
    float* lstm_p   = (float*)p1;
    float* scores_p = (float*)p2;
    float* logits_p = (float*)p3;
    __nv_bfloat16* bufA   = (__nv_bfloat16*)pa;
    __nv_bfloat16* bufW   = (__nv_bfloat16*)pw;
    __nv_bfloat16* bufBIG = (__nv_bfloat16*)pbig;
    __nv_bfloat16* bufT   = (__nv_bfloat16*)pt;

    zero_kernel<<<32, 256>>>();
    cvt_whh<<<2048, 256>>>(W_hh);

    // 1) xp = x @ W_ih^T + b_ih + b_hh       M=16384, N=2048, K3=1536
    cvt_split<<<16384, 256>>>(x, bufA, 512, 1);
    cvt_split<<<2048, 256>>>(W_ih, bufW, 512, 0);
    mma_gemm<<<dim3(16, 128, 1), 128>>>(
        bufA, bufW, xp_p, b_ih, b_hh, 1536, 2048, 0, 0, 0);

    // 2) persistent LSTM recurrence (tensor-core, fixed staging)
    lstm_rec_kernel<<<NBLK, 256>>>();

    // 3) scores = lstm @ Wa^T + ba           M=16384, N=512, K3=1536
    cvt_split<<<16384, 256>>>(lstm_p, bufA, 512, 1);
    cvt_split<<<512, 256>>>(Wa, bufW, 512, 0);
    mma_gemm<<<dim3(4, 128, 1), 128>>>(
        bufA, bufW, scores_p, ba, nullptr, 1536, 512, 0, 0, 0);

    // 4) logits[b] = scores[b] @ scores[b]^T M=2048, N=2048, K3=1536, batched
    cvt_split<<<16384, 256>>>(scores_p, bufA, 512, 1);
    cvt_split<<<16384, 256>>>(scores_p, bufBIG, 512, 0);
    mma_gemm<<<dim3(16, 16, 8), 128>>>(
        bufA, bufBIG, logits_p, nullptr, nullptr, 1536, 2048,
        (size_t)2048 * 1536, (size_t)2048 * 1536, (size_t)2048 * 2048);

    // 5) att = softmax(logits) in place
    softmax_kernel<<<16384, 256>>>();

    // 6) out[b] = att[b] @ lstm[b]           M=2048, N=512, K3=6144, batched
    cvt_split<<<65536, 256>>>(logits_p, bufBIG, 2048, 1);
    cvt_lstmT<<<16384, 256>>>();
    mma_gemm<<<dim3(4, 16, 8), 128>>>(
        bufBIG, bufT, out, nullptr, nullptr, 6144, 512,
        (size_t)2048 * 6144, (size_t)512 * 6144, (size_t)2048 * 512);
}

// round 13
// speedup vs baseline: 1.3643x; 1.0944x over previous
#include <cuda_runtime.h>
#include <cuda_bf16.h>
#include <math.h>
#include <stdint.h>

#define B_    8
#define S_    2048
#define H_    512
#define G4_   2048
#define NBLK  128

// ---------------------------------------------------------------------------
// Static device scratch (no allocation allowed)
// ---------------------------------------------------------------------------
__device__ float    g_xp[(size_t)B_ * S_ * G4_];      // 128 MiB (reused as bf16 scores buf)
__device__ float    g_logits[(size_t)B_ * S_ * S_];   // 128 MiB
__device__ unsigned g_bar[S_];                        // per-step barrier counters

// bf16 h exchange: [phase][hi 4096 | lo 4096], phase stride 8192 elems
__device__ __align__(16) __nv_bfloat16 g_hbf[2 * 8192];

// bf16 operand buffers
__device__ __align__(16) __nv_bfloat16 g_bufA[(size_t)16384 * 1536];   // 50 MiB
__device__ __align__(16) __nv_bfloat16 g_bufW[(size_t)2048 * 1536];    // 6 MiB
__device__ __align__(16) __nv_bfloat16 g_bufBIG[(size_t)16384 * 4096]; // 134 MiB
__device__ __align__(16) __nv_bfloat16 g_bufT[(size_t)8 * 512 * 2048]; // 16 MiB

// gathered split-bf16 W_hh for the recurrence: [128 blk][16 rows][512 k]
__device__ __align__(16) __nv_bfloat16 g_Whi[(size_t)128 * 16 * 512];  // 2 MiB
__device__ __align__(16) __nv_bfloat16 g_Wlo[(size_t)128 * 16 * 512];  // 2 MiB

// fast activations (MUFU-based, rel err ~1e-6, saturate correctly at +-inf)
__device__ __forceinline__ float fsigm(float x) {
    return __fdividef(1.0f, 1.0f + __expf(-x));
}
__device__ __forceinline__ float ftanh(float x) {
    return 1.0f - __fdividef(2.0f, __expf(2.0f * x) + 1.0f);
}

__device__ __forceinline__ uint32_t smem_u32(const void* p) {
    uint32_t a;
    asm("{ .reg .u64 t; cvta.to.shared.u64 t, %1; cvt.u32.u64 %0, t; }"
        : "=r"(a) : "l"(p));
    return a;
}

__device__ __forceinline__ void ldm_x4(uint32_t* r, uint32_t addr) {
    asm volatile("ldmatrix.sync.aligned.m8n8.x4.shared.b16 {%0,%1,%2,%3}, [%4];"
        : "=r"(r[0]), "=r"(r[1]), "=r"(r[2]), "=r"(r[3]) : "r"(addr));
}
__device__ __forceinline__ void ldm_x2t(uint32_t* r, uint32_t addr) {
    asm volatile("ldmatrix.sync.aligned.m8n8.x2.trans.shared.b16 {%0,%1}, [%2];"
        : "=r"(r[0]), "=r"(r[1]) : "r"(addr));
}

__device__ __forceinline__ void mma16816(float* c, const uint32_t* a,
                                         const uint32_t* b) {
    asm volatile(
        "mma.sync.aligned.m16n8k16.row.col.f32.bf16.bf16.f32 "
        "{%0,%1,%2,%3}, {%4,%5,%6,%7}, {%8,%9}, {%0,%1,%2,%3};"
        : "+f"(c[0]), "+f"(c[1]), "+f"(c[2]), "+f"(c[3])
        : "r"(a[0]), "r"(a[1]), "r"(a[2]), "r"(a[3]), "r"(b[0]), "r"(b[1]));
}

// ---------------------------------------------------------------------------
// Zero barrier counters + initial hidden state (phase 0 of g_hbf)
// ---------------------------------------------------------------------------
__global__ void zero_kernel() {
    int i = blockIdx.x * 256 + threadIdx.x;   // 8192 threads
    if (i < S_) g_bar[i] = 0u;
    if (i < 4096) ((uint32_t*)g_hbf)[i] = 0u;  // first 16KB = phase 0 hi+lo
}

// ---------------------------------------------------------------------------
// Gather + split W_hh into per-block row order: lr = gate*4 + jj
// ---------------------------------------------------------------------------
__global__ void __launch_bounds__(256)
cvt_whh(const float* __restrict__ W)
{
    size_t o = ((size_t)blockIdx.x * 256 + threadIdx.x) * 2;  // 2048 blocks
    int k  = (int)(o & 511);
    int lr = (int)((o >> 9) & 15);
    int blk = (int)(o >> 13);
    int gi = lr >> 2, jj = lr & 3;
    float2 x = *(const float2*)&W[(size_t)(gi * 512 + blk * 4 + jj) * 512 + k];
    __nv_bfloat16 h0 = __float2bfloat16(x.x);
    __nv_bfloat16 h1 = __float2bfloat16(x.y);
    __nv_bfloat16 l0 = __float2bfloat16(x.x - __bfloat162float(h0));
    __nv_bfloat16 l1 = __float2bfloat16(x.y - __bfloat162float(h1));
    __nv_bfloat162 Hv; Hv.x = h0; Hv.y = h1;
    __nv_bfloat162 Lv; Lv.x = l0; Lv.y = l1;
    *(__nv_bfloat162*)(g_Whi + o) = Hv;
    *(__nv_bfloat162*)(g_Wlo + o) = Lv;
}

// ---------------------------------------------------------------------------
// fp32 -> split-bf16 conversion, contiguous [R,K] -> [R,3K]
// amode=1 (A operand): segments (hi, lo, hi)
// amode=0 (B operand): segments (hi, hi, lo)
// ---------------------------------------------------------------------------
__global__ void __launch_bounds__(256)
cvt_split(const float* __restrict__ in, __nv_bfloat16* __restrict__ out,
          int K, int amode)
{
    size_t e = ((size_t)blockIdx.x * 256 + threadIdx.x) * 2;
    size_t r = e / (size_t)K;
    int k = (int)(e - r * (size_t)K);
    float2 x = *(const float2*)(in + e);
    __nv_bfloat16 h0 = __float2bfloat16(x.x);
    __nv_bfloat16 h1 = __float2bfloat16(x.y);
    __nv_bfloat16 l0 = __float2bfloat16(x.x - __bfloat162float(h0));
    __nv_bfloat16 l1 = __float2bfloat16(x.y - __bfloat162float(h1));
    __nv_bfloat162 Hv; Hv.x = h0; Hv.y = h1;
    __nv_bfloat162 Lv; Lv.x = l0; Lv.y = l1;
    __nv_bfloat16* o = out + r * (size_t)(3 * K) + k;
    *(__nv_bfloat162*)o = Hv;
    *(__nv_bfloat162*)(o + K) = amode ? Lv : Hv;
    *(__nv_bfloat162*)(o + 2 * K) = amode ? Hv : Lv;
}

// split store helper for the scores-GEMM epilogue
__device__ __forceinline__ void store_split(__nv_bfloat16* P1, __nv_bfloat16* P2,
                                            int r, int col, float2 v)
{
    __nv_bfloat162 h = __float22bfloat162_rn(v);
    float2 lr = make_float2(v.x - __low2float(h), v.y - __high2float(h));
    __nv_bfloat162 l = __float22bfloat162_rn(lr);
    *(__nv_bfloat162*)(P1 + (size_t)r * 1024 + col) = h;
    *(__nv_bfloat162*)(P1 + (size_t)r * 1024 + 512 + col) = l;
    *(__nv_bfloat162*)(P2 + (size_t)r * 512 + col) = h;
}

// ---------------------------------------------------------------------------
// Tensor-core bf16 GEMM via mma.sync.
// A: [M, lda] bf16, chunk c reads cols c*32..; B: [N, ldb], chunk wraps at
// kbchunks (enables A=[hi|lo] x B=[hi|hi] 2-segment products).
// emode 0: C fp32 (+bias,+bias2). emode 1: write split-bf16 to P1 (2-seg,
// row 1024) and P2 (hi, row 512) instead of C.
// ---------------------------------------------------------------------------
__global__ void __launch_bounds__(128, 1)
mma_gemm(const __nv_bfloat16* __restrict__ A, const __nv_bfloat16* __restrict__ B,
         float* __restrict__ C,
         const float* __restrict__ bias, const float* __restrict__ bias2,
         int K3, int lda, int ldb, int kbchunks, int ldc,
         size_t sA, size_t sB, size_t sC,
         __nv_bfloat16* P1, __nv_bfloat16* P2, int emode)
{
    __shared__ __align__(16) char sm[2][2][128 * 80];

    const int z = blockIdx.z;
    A += (size_t)z * sA;
    B += (size_t)z * sB;
    C += (size_t)z * sC;
    const int m0 = blockIdx.y * 128;
    const int n0 = blockIdx.x * 128;

    const int tid = threadIdx.x;
    const int lane = tid & 31;
    const int wid = tid >> 5;
    const int wm = wid & 1;
    const int wn = wid >> 1;

    const int NC = K3 >> 5;

    float acc[4][8][4];
#pragma unroll
    for (int i = 0; i < 4; i++)
#pragma unroll
        for (int j = 0; j < 8; j++)
#pragma unroll
            for (int q = 0; q < 4; q++) acc[i][j][q] = 0.0f;

#define LOAD_STAGE(st, ck, bo) do {                                           \
        _Pragma("unroll")                                                     \
        for (int _i = 0; _i < 8; _i++) {                                      \
            int _u = tid + _i * 128;                                          \
            int _ab = _u >> 9;                                                \
            int _v = _u & 511;                                                \
            int _r = _v >> 2, _cu = _v & 3;                                   \
            const __nv_bfloat16* _g = _ab                                     \
                ? B + (size_t)(n0 + _r) * ldb + (bo) + _cu * 8                \
                : A + (size_t)(m0 + _r) * lda + (ck) * 32 + _cu * 8;          \
            uint32_t _s = smem_u32(&sm[st][_ab][_r * 80 + _cu * 16]);         \
            asm volatile("cp.async.cg.shared.global [%0], [%1], 16;"          \
                         :: "r"(_s), "l"(_g));                                \
        }                                                                     \
        asm volatile("cp.async.commit_group;" ::: "memory");                  \
    } while (0)

    LOAD_STAGE(0, 0, 0);

    const int a_row_in = (lane & 15);
    const int a_koff   = (lane >> 4) * 16;
    const int b_row_in = (lane & 7) + ((lane >> 4) << 3);
    const int b_koff   = ((lane >> 3) & 1) * 16;

    for (int c = 0; c < NC; c++) {
        const int buf = c & 1;
        if (c + 1 < NC) {
            LOAD_STAGE(buf ^ 1, c + 1, ((c + 1) % kbchunks) * 32);
            asm volatile("cp.async.wait_group 1;" ::: "memory");
        } else {
            asm volatile("cp.async.wait_group 0;" ::: "memory");
        }
        __syncthreads();

        const uint32_t sAb = smem_u32(&sm[buf][0][0]);
        const uint32_t sBb = smem_u32(&sm[buf][1][0]);

#pragma unroll
        for (int s = 0; s < 2; s++) {
            uint32_t a[4][4];
#pragma unroll
            for (int mi = 0; mi < 4; mi++) {
                uint32_t addr = sAb +
                    (uint32_t)(wm * 64 + mi * 16 + a_row_in) * 80 +
                    s * 32 + a_koff;
                ldm_x4(a[mi], addr);
            }
            uint32_t b[8][2];
#pragma unroll
            for (int t4 = 0; t4 < 4; t4++) {
                uint32_t r[4];
                uint32_t addr = sBb +
                    (uint32_t)(wn * 64 + t4 * 16 + b_row_in) * 80 +
                    s * 32 + b_koff;
                ldm_x4(r, addr);
                b[2 * t4][0] = r[0]; b[2 * t4][1] = r[1];
                b[2 * t4 + 1][0] = r[2]; b[2 * t4 + 1][1] = r[3];
            }
#pragma unroll
            for (int mi = 0; mi < 4; mi++)
#pragma unroll
                for (int nj = 0; nj < 8; nj++)
                    mma16816(acc[mi][nj], a[mi], b[nj]);
        }
        __syncthreads();
    }

    const int g = lane >> 2, tig = lane & 3;
#pragma unroll
    for (int mi = 0; mi < 4; mi++) {
        const int r0 = m0 + wm * 64 + mi * 16 + g;
#pragma unroll
        for (int nj = 0; nj < 8; nj++) {
            const int col = n0 + wn * 64 + nj * 8 + tig * 2;
            float b0 = 0.0f, b1 = 0.0f;
            if (bias)  { b0 += bias[col];  b1 += bias[col + 1]; }
            if (bias2) { b0 += bias2[col]; b1 += bias2[col + 1]; }
            float2 v0 = make_float2(acc[mi][nj][0] + b0, acc[mi][nj][1] + b1);
            float2 v1 = make_float2(acc[mi][nj][2] + b0, acc[mi][nj][3] + b1);
            if (emode == 0) {
                *(float2*)(C + (size_t)r0 * ldc + col) = v0;
                *(float2*)(C + (size_t)(r0 + 8) * ldc + col) = v1;
            } else {
                store_split(P1, P2, r0, col, v0);
                store_split(P1, P2, r0 + 8, col, v1);
            }
        }
    }
#undef LOAD_STAGE
}

// ---------------------------------------------------------------------------
// Persistent LSTM recurrence v5 — tensor cores + bf16 h exchange + fast act.
// Producer (32 act threads) writes h as split bf16 to g_hbf AND lstm operand
// buffers (bufA 3-seg rows, bufT transposed hi) directly — no fp32 h anywhere.
// ---------------------------------------------------------------------------
__global__ void __launch_bounds__(256, 1)
lstm_rec_kernel(__nv_bfloat16* __restrict__ bufA, __nv_bfloat16* __restrict__ bufT)
{
    __shared__ __align__(16) char  s_hT[16384];   // hi @0 (8KB), lo @8192; W stage at startup
    __shared__ float s_red[8][16][8];             // per-warp 16x8 partials
    __shared__ float s_cs[32];                    // cell state (b*4+q)

    const int tid  = threadIdx.x;
    const int blk  = blockIdx.x;
    const int j0   = blk * 4;
    const int w    = tid >> 5;
    const int lane = tid & 31;

    const uint32_t hT_u32 = smem_u32(s_hT);

    // ---- startup: load W fragments into registers (once)
    uint32_t whi[4][4], wlo[4][4];
    {
        const uint4* srcH = (const uint4*)(g_Whi + (size_t)blk * 8192);
        uint4* dst = (uint4*)s_hT;
        for (int i = tid; i < 1024; i += 256) dst[i] = srcH[i];
        __syncthreads();
#pragma unroll
        for (int kw = 0; kw < 4; kw++) {
            uint32_t addr = hT_u32 + (uint32_t)(lane & 15) * 1024 +
                            (uint32_t)(w * 64 + kw * 16) * 2 + ((lane >> 4) * 16);
            ldm_x4(whi[kw], addr);
        }
        __syncthreads();
        const uint4* srcL = (const uint4*)(g_Wlo + (size_t)blk * 8192);
        for (int i = tid; i < 1024; i += 256) dst[i] = srcL[i];
        __syncthreads();
#pragma unroll
        for (int kw = 0; kw < 4; kw++) {
            uint32_t addr = hT_u32 + (uint32_t)(lane & 15) * 1024 +
                            (uint32_t)(w * 64 + kw * 16) * 2 + ((lane >> 4) * 16);
            ldm_x4(wlo[kw], addr);
        }
    }
    if (tid < 32) s_cs[tid] = 0.0f;
    __syncthreads();

    for (int t = 0; t < S_; t++) {
        const int cur = t & 1;

        // xp prefetch (overlaps everything until activation)
        float xi = 0.f, xf = 0.f, xg = 0.f, xo = 0.f;
        if (tid < 32) {
            int b = tid >> 2, q = tid & 3;
            size_t base = ((size_t)b * S_ + t) * G4_ + (j0 + q);
            xi = g_xp[base];
            xf = g_xp[base + 512];
            xg = g_xp[base + 1024];
            xo = g_xp[base + 1536];
        }

        // stage h: already split bf16 in L2 (16KB) -> SMEM, 4x LDG.128/STS.128
        {
            const uint4* hsrc = (const uint4*)(g_hbf + (size_t)cur * 8192);
#pragma unroll
            for (int i = 0; i < 4; i++) {
                int u = tid + i * 256;           // 0..1023 16B units (hi then lo)
                *(uint4*)(s_hT + u * 16) = __ldcg(&hsrc[u]);
            }
        }
        __syncthreads();

        // 12 mma.sync: acc = Whi*hhi, acc2 = Wlo*hhi + Whi*hlo
        float acc[4] = {0.f, 0.f, 0.f, 0.f};
        float acc2[4] = {0.f, 0.f, 0.f, 0.f};
#pragma unroll
        for (int kw = 0; kw < 4; kw++) {
            const int k0 = w * 64 + kw * 16;
            uint32_t bh[2], bl[2];
            uint32_t ab = hT_u32 + (uint32_t)(k0 + (lane & 15)) * 16;
            ldm_x2t(bh, ab);
            ldm_x2t(bl, ab + 8192);
            mma16816(acc,  whi[kw], bh);
            mma16816(acc2, wlo[kw], bh);
            mma16816(acc2, whi[kw], bl);
        }
        {
            const int row = lane >> 2, col = (lane & 3) * 2;
            *(float2*)&s_red[w][row][col] =
                make_float2(acc[0] + acc2[0], acc[1] + acc2[1]);
            *(float2*)&s_red[w][row + 8][col] =
                make_float2(acc[2] + acc2[2], acc[3] + acc2[3]);
        }
        __syncthreads();

        // activation: thread (b,q)
        if (tid < 32) {
            int b = tid >> 2, q = tid & 3;
            float gsum[4];
#pragma unroll
            for (int g = 0; g < 4; g++) {
                float s = 0.0f;
#pragma unroll
                for (int w2 = 0; w2 < 8; w2++) s += s_red[w2][g * 4 + q][b];
                gsum[g] = s;
            }
            float ig = gsum[0] + xi;
            float fg = gsum[1] + xf;
            float gg = gsum[2] + xg;
            float og = gsum[3] + xo;
            float cc = fsigm(fg) * s_cs[tid] + fsigm(ig) * ftanh(gg);
            float hh = fsigm(og) * ftanh(cc);
            s_cs[tid] = cc;

            int j = j0 + q;
            __nv_bfloat16 hi = __float2bfloat16(hh);
            __nv_bfloat16 lo = __float2bfloat16(hh - __bfloat162float(hi));
            __nv_bfloat16* hb = g_hbf + (size_t)(cur ^ 1) * 8192;
            hb[j * 8 + b] = hi;
            hb[4096 + j * 8 + b] = lo;
            // lstm operand buffers (A 3-seg row, B transposed hi)
            size_t m = (size_t)b * 2048 + t;
            bufA[m * 1536 + j] = hi;
            bufA[m * 1536 + 512 + j] = lo;
            bufA[m * 1536 + 1024 + j] = hi;
            bufT[((size_t)b * 512 + j) * 2048 + t] = hi;
        }

        // grid barrier
        __threadfence();
        __syncthreads();
        if (tid == 0) {
            atomicAdd(&g_bar[t], 1u);
            volatile unsigned* p = &g_bar[t];
            while (*p < (unsigned)NBLK) {}
        }
        __syncthreads();
    }
}

// ---------------------------------------------------------------------------
// Row softmax over g_logits (read-only) -> 2-seg split-bf16 att in attout.
// 16384 rows of 2048; attout rows 4096 wide: hi @[0,2048), lo @[2048,4096).
// ---------------------------------------------------------------------------
__global__ void __launch_bounds__(256) softmax_kernel(__nv_bfloat16* __restrict__ attout) {
    __shared__ float red[8];
    const float* p = g_logits + (size_t)blockIdx.x * 2048;
    const int tid = threadIdx.x;

    float4 v0 = *(const float4*)(p + tid * 4);
    float4 v1 = *(const float4*)(p + 1024 + tid * 4);

    float m = fmaxf(fmaxf(fmaxf(v0.x, v0.y), fmaxf(v0.z, v0.w)),
                    fmaxf(fmaxf(v1.x, v1.y), fmaxf(v1.z, v1.w)));
#pragma unroll
    for (int off = 16; off; off >>= 1)
        m = fmaxf(m, __shfl_xor_sync(0xffffffffu, m, off));
    if ((tid & 31) == 0) red[tid >> 5] = m;
    __syncthreads();
    m = red[0];
#pragma unroll
    for (int w = 1; w < 8; w++) m = fmaxf(m, red[w]);
    __syncthreads();

    v0.x = expf(v0.x - m); v0.y = expf(v0.y - m);
    v0.z = expf(v0.z - m); v0.w = expf(v0.w - m);
    v1.x = expf(v1.x - m); v1.y = expf(v1.y - m);
    v1.z = expf(v1.z - m); v1.w = expf(v1.w - m);

    float s = v0.x + v0.y + v0.z + v0.w + v1.x + v1.y + v1.z + v1.w;
#pragma unroll
    for (int off = 16; off; off >>= 1)
        s += __shfl_xor_sync(0xffffffffu, s, off);
    if ((tid & 31) == 0) red[tid >> 5] = s;
    __syncthreads();
    s = red[0];
#pragma unroll
    for (int w = 1; w < 8; w++) s += red[w];

    float inv = 1.0f / s;
    v0.x *= inv; v0.y *= inv; v0.z *= inv; v0.w *= inv;
    v1.x *= inv; v1.y *= inv; v1.z *= inv; v1.w *= inv;

    __nv_bfloat16* o = attout + (size_t)blockIdx.x * 4096;
#pragma unroll
    for (int half = 0; half < 2; half++) {
        float4 v = half ? v1 : v0;
        int c0 = half * 1024 + tid * 4;
        __nv_bfloat162 h01 = __float22bfloat162_rn(make_float2(v.x, v.y));
        __nv_bfloat162 h23 = __float22bfloat162_rn(make_float2(v.z, v.w));
        float2 l01f = make_float2(v.x - __low2float(h01), v.y - __high2float(h01));
        float2 l23f = make_float2(v.z - __low2float(h23), v.w - __high2float(h23));
        __nv_bfloat162 l01 = __float22bfloat162_rn(l01f);
        __nv_bfloat162 l23 = __float22bfloat162_rn(l23f);
        uint2 H; H.x = *(uint32_t*)&h01; H.y = *(uint32_t*)&h23;
        uint2 L; L.x = *(uint32_t*)&l01; L.y = *(uint32_t*)&l23;
        *(uint2*)(o + c0) = H;
        *(uint2*)(o + 2048 + c0) = L;
    }
}

// ---------------------------------------------------------------------------
// Launch
// ---------------------------------------------------------------------------
extern "C" void kernel_launch(void* const* d_in, const int* in_sizes, int n_in,
                              void* d_out, int out_size)
{
    const float* x    = (const float*)d_in[0];  // [B,S,I]
    const float* W_ih = (const float*)d_in[1];  // [4H,I]
    const float* W_hh = (const float*)d_in[2];  // [4H,H]
    const float* b_ih = (const float*)d_in[3];  // [4H]
    const float* b_hh = (const float*)d_in[4];  // [4H]
    const float* Wa   = (const float*)d_in[5];  // [H,H]
    const float* ba   = (const float*)d_in[6];  // [H]
    float* out = (float*)d_out;                 // [B,S,H] fp32

    void *p0, *p3, *pa, *pw, *pbig, *pt;
    cudaGetSymbolAddress(&p0, g_xp);
    cudaGetSymbolAddress(&p3, g_logits);
    cudaGetSymbolAddress(&pa, g_bufA);
    cudaGetSymbolAddress(&pw, g_bufW);
    cudaGetSymbolAddress(&pbig, g_bufBIG);
    cudaGetSymbolAddress(&pt, g_bufT);
    float* xp_p     = (float*)p0;
    float* logits_p = (float*)p3;
    __nv_bfloat16* bufA   = (__nv_bfloat16*)pa;
    __nv_bfloat16* bufW   = (__nv_bfloat16*)pw;
    __nv_bfloat16* bufBIG = (__nv_bfloat16*)pbig;
    __nv_bfloat16* bufT   = (__nv_bfloat16*)pt;
    __nv_bfloat16* scoresbf = (__nv_bfloat16*)p0;   // g_xp reused after recurrence

    zero_kernel<<<32, 256>>>();
    cvt_whh<<<2048, 256>>>(W_hh);

    // 1) xp = x @ W_ih^T + b_ih + b_hh       M=16384, N=2048, K3=1536 (3-seg)
    cvt_split<<<16384, 256>>>(x, bufA, 512, 1);
    cvt_split<<<2048, 256>>>(W_ih, bufW, 512, 0);
    mma_gemm<<<dim3(16, 128, 1), 128>>>(
        bufA, bufW, xp_p, b_ih, b_hh,
        1536, 1536, 1536, 48, 2048, 0, 0, 0, nullptr, nullptr, 0);

    // 2) persistent LSTM recurrence — writes bufA (lstm 3-seg) + bufT (hi^T)
    lstm_rec_kernel<<<NBLK, 256>>>(bufA, bufT);

    // 3) scores = lstm @ Wa^T + ba -> split-bf16 operands directly
    //    P1 = scoresbf (2-seg, row 1024) in g_xp; P2 = bufBIG (hi, row 512)
    cvt_split<<<512, 256>>>(Wa, bufW, 512, 0);
    mma_gemm<<<dim3(4, 128, 1), 128>>>(
        bufA, bufW, logits_p /*unused*/, ba, nullptr,
        1536, 1536, 1536, 48, 512, 0, 0, 0, scoresbf, bufBIG, 1);

    // 4) logits[b] = scores[b] @ scores[b]^T   (2-seg A x wrapped-hi B)
    mma_gemm<<<dim3(16, 16, 8), 128>>>(
        scoresbf, bufBIG, logits_p, nullptr, nullptr,
        1024, 1024, 512, 16, 2048,
        (size_t)2048 * 1024, (size_t)2048 * 512, (size_t)2048 * 2048,
        nullptr, nullptr, 0);

    // 5) att = softmax(logits) -> 2-seg bf16 straight into bufBIG (rows 4096)
    softmax_kernel<<<16384, 256>>>(bufBIG);

    // 6) out[b] = att[b] @ lstm[b]   (2-seg A x wrapped-hi B=bufT)
    mma_gemm<<<dim3(4, 16, 8), 128>>>(
        bufBIG, bufT, out, nullptr, nullptr,
        4096, 4096, 2048, 64, 512,
        (size_t)2048 * 4096, (size_t)512 * 2048, (size_t)2048 * 512,
        nullptr, nullptr, 0);
}